// round 5
// baseline (speedup 1.0000x reference)
#include <cuda_runtime.h>

// ---------------------------------------------------------------------------
// OpticFlowMask fused persistent kernel: 3 phases + software grid barrier.
// B=12, H=192, W=640.
// Output layout (float32): [motion_mask (N)][bwd_flow (2N)][seg_ref (N)]
// ---------------------------------------------------------------------------

#define BB    12
#define HH    192
#define WW    640
#define HWSZ  (HH * WW)                 // 122880
#define NPIX  (BB * HWSZ)               // 1474560
#define TPB   256
#define GRID  480                       // co-resident: <= 4/SM * 148 SMs
#define ITERS 3                         // GRID*TPB*ITERS*4 == NPIX exactly
#define QSTRIDE (GRID * TPB)            // 122880 quads per sweep
#define EPSF  1e-7f
#define THR   0.98f
#define FINF  __int_as_float(0x7f800000)
#define FNINF __int_as_float(0xff800000)

__device__ int    g_winner[NPIX];
__device__ float4 g_payload[NPIX];          // (-fx, -fy, seg, c)
__device__ float  g_part[6][GRID];          // 0 fmin,1 fmax,2 smin,3 smax,4 cmin,5 cmax
__device__ unsigned g_bar_count = 0;
__device__ unsigned g_bar_gen   = 0;

__device__ __forceinline__ void grid_sync() {
    __syncthreads();
    if (threadIdx.x == 0) {
        __threadfence();
        unsigned gen = *(volatile unsigned*)&g_bar_gen;
        if (atomicAdd(&g_bar_count, 1u) == GRID - 1) {
            g_bar_count = 0;
            __threadfence();
            atomicAdd(&g_bar_gen, 1u);
        } else {
            while (*(volatile unsigned*)&g_bar_gen == gen) { }
        }
        __threadfence();
    }
    __syncthreads();
}

// block-wide min/max reduce; results broadcast to all threads via scratch[16]
__device__ __forceinline__ void blk_minmax(float vmin, float vmax, float* scr,
                                           float& omin, float& omax) {
#pragma unroll
    for (int o = 16; o; o >>= 1) {
        vmin = fminf(vmin, __shfl_xor_sync(0xffffffffu, vmin, o));
        vmax = fmaxf(vmax, __shfl_xor_sync(0xffffffffu, vmax, o));
    }
    int w = threadIdx.x >> 5, l = threadIdx.x & 31;
    if (l == 0) { scr[w] = vmin; scr[8 + w] = vmax; }
    __syncthreads();
    if (threadIdx.x == 0) {
        float a = scr[0], bmax = scr[8];
#pragma unroll
        for (int i = 1; i < 8; i++) {
            a = fminf(a, scr[i]);
            bmax = fmaxf(bmax, scr[8 + i]);
        }
        scr[0] = a; scr[8] = bmax;
    }
    __syncthreads();
    omin = scr[0]; omax = scr[8];
    __syncthreads();
}

// reduce one (min,max) slot pair of g_part across GRID entries, broadcast
__device__ __forceinline__ void part_minmax(int smin_slot, int smax_slot,
                                            float* scr, float& omin, float& omax) {
    int t = threadIdx.x;
    float vmin = g_part[smin_slot][t];
    float vmax = g_part[smax_slot][t];
    if (t + TPB < GRID) {
        vmin = fminf(vmin, g_part[smin_slot][t + TPB]);
        vmax = fmaxf(vmax, g_part[smax_slot][t + TPB]);
    }
    blk_minmax(vmin, vmax, scr, omin, omax);
}

// static flow for 4 consecutive x positions at fixed y
__device__ __forceinline__ void static_flow4(const float* sP, const float* siK,
                                             float x0, float y, const float4& d4,
                                             float* sx, float* sy) {
    const float dv[4] = {d4.x, d4.y, d4.z, d4.w};
#pragma unroll
    for (int i = 0; i < 4; i++) {
        float x = x0 + (float)i;
        float dx = siK[0] * x + (siK[1] * y + siK[2]);
        float dy = siK[3] * x + (siK[4] * y + siK[5]);
        float dz = siK[6] * x + (siK[7] * y + siK[8]);
        float d = dv[i];
        float cx = d * dx, cy = d * dy, cz = d * dz;
        float c0 = sP[0] * cx + sP[1] * cy + sP[2]  * cz + sP[3];
        float c1 = sP[4] * cx + sP[5] * cy + sP[6]  * cz + sP[7];
        float c2 = sP[8] * cx + sP[9] * cy + sP[10] * cz + sP[11];
        float den = c2 + EPSF;
        sx[i] = c0 / den - x;
        sy[i] = c1 / den - y;
    }
}

__global__ void __launch_bounds__(TPB, 4) k_fused(
        const float* __restrict__ flow, const float* __restrict__ depth,
        const float* __restrict__ Kmat, const float* __restrict__ invK,
        const float* __restrict__ pose, const int* __restrict__ seg,
        float* __restrict__ out) {
    // per-batch matrices: 21 floats per batch (P[12] then invK3x3[9])
    __shared__ float sMat[BB * 21];
    __shared__ float scr[16];
    {
        int t = threadIdx.x;
        if (t < BB * 21) {
            int b = t / 21, e = t - b * 21;
            if (e < 12) {
                int i = e >> 2, j = e & 3;
                const float* Kb = Kmat + b * 16;
                const float* Pb = pose + b * 16;
                sMat[t] = Kb[i*4+0]*Pb[0*4+j] + Kb[i*4+1]*Pb[1*4+j] +
                          Kb[i*4+2]*Pb[2*4+j] + Kb[i*4+3]*Pb[3*4+j];
            } else {
                int e2 = e - 12;
                int r = e2 / 3, c = e2 - r * 3;
                sMat[t] = invK[b * 16 + r * 4 + c];
            }
        }
        __syncthreads();
    }

    const int base = blockIdx.x * TPB + threadIdx.x;

    // ---------------- Phase 1: flow/static min-max + winner reset -----------
    {
        float fmn = FINF, fmx = FNINF, smn = FINF, smx = FNINF;
#pragma unroll
        for (int i = 0; i < ITERS; i++) {
            int q = i * QSTRIDE + base;
            int px0 = q * 4;
            int b = px0 / HWSZ;
            int p = px0 - b * HWSZ;
            int y = p / WW, x0 = p - y * WW;
            const float4 fx4 = *(const float4*)(flow + b * 2 * HWSZ + p);
            const float4 fy4 = *(const float4*)(flow + b * 2 * HWSZ + HWSZ + p);
            const float4 d4  = *(const float4*)(depth + px0);
            *(int4*)(g_winner + px0) = make_int4(-1, -1, -1, -1);

            float sx[4], sy[4];
            static_flow4(&sMat[b*21], &sMat[b*21+12], (float)x0, (float)y, d4, sx, sy);

            fmn = fminf(fmn, fminf(fminf(fx4.x, fx4.y), fminf(fx4.z, fx4.w)));
            fmn = fminf(fmn, fminf(fminf(fy4.x, fy4.y), fminf(fy4.z, fy4.w)));
            fmx = fmaxf(fmx, fmaxf(fmaxf(fx4.x, fx4.y), fmaxf(fx4.z, fx4.w)));
            fmx = fmaxf(fmx, fmaxf(fmaxf(fy4.x, fy4.y), fmaxf(fy4.z, fy4.w)));
            smn = fminf(fminf(fminf(fminf(sx[0], sx[1]), fminf(sx[2], sx[3])), smn),
                        fminf(fminf(sy[0], sy[1]), fminf(sy[2], sy[3])));
            smx = fmaxf(fmaxf(fmaxf(fmaxf(sx[0], sx[1]), fmaxf(sx[2], sx[3])), smx),
                        fmaxf(fmaxf(sy[0], sy[1]), fmaxf(sy[2], sy[3])));
        }
        float a, bb_;
        blk_minmax(fmn, fmx, scr, a, bb_);
        if (threadIdx.x == 0) { g_part[0][blockIdx.x] = a; g_part[1][blockIdx.x] = bb_; }
        blk_minmax(smn, smx, scr, a, bb_);
        if (threadIdx.x == 0) { g_part[2][blockIdx.x] = a; g_part[3][blockIdx.x] = bb_; }
    }
    grid_sync();

    // ---------------- Phase 2: check + payload + winner election ------------
    float c_save[ITERS * 4];
    {
        float fmn, fmx, smn, smx;
        part_minmax(0, 1, scr, fmn, fmx);
        part_minmax(2, 3, scr, smn, smx);
        float finv = 2.0f / (fmx - fmn), sinv = 2.0f / (smx - smn);

        float cmn = FINF, cmx = FNINF;
#pragma unroll
        for (int i = 0; i < ITERS; i++) {
            int q = i * QSTRIDE + base;
            int px0 = q * 4;
            int b = px0 / HWSZ;
            int p = px0 - b * HWSZ;
            int y = p / WW, x0 = p - y * WW;
            const float4 fx4 = *(const float4*)(flow + b * 2 * HWSZ + p);
            const float4 fy4 = *(const float4*)(flow + b * 2 * HWSZ + HWSZ + p);
            const float4 d4  = *(const float4*)(depth + px0);
            const int4  sg4  = *(const int4*)(seg + px0);

            float sx[4], sy[4];
            static_flow4(&sMat[b*21], &sMat[b*21+12], (float)x0, (float)y, d4, sx, sy);

            const float fxv[4] = {fx4.x, fx4.y, fx4.z, fx4.w};
            const float fyv[4] = {fy4.x, fy4.y, fy4.z, fy4.w};
            const int   sgv[4] = {sg4.x, sg4.y, sg4.z, sg4.w};
#pragma unroll
            for (int j = 0; j < 4; j++) {
                float ddx = (fxv[j] - fmn) * finv - (sx[j] - smn) * sinv;
                float ddy = (fyv[j] - fmn) * finv - (sy[j] - smn) * sinv;
                float c = sqrtf(ddx * ddx + ddy * ddy);
                c_save[i * 4 + j] = c;
                cmn = fminf(cmn, c);
                cmx = fmaxf(cmx, c);
                g_payload[px0 + j] =
                    make_float4(-fxv[j], -fyv[j], sgv[j] ? 1.0f : 0.0f, c);
                // winner election: jnp.round = ties-to-even; clip after cast
                int cxi = min(max((int)rintf((float)(x0 + j) + fxv[j]), 0), WW - 1);
                int cyi = min(max((int)rintf((float)y + fyv[j]), 0), HH - 1);
                atomicMax(&g_winner[b * HWSZ + cyi * WW + cxi], p + j);
            }
        }
        float a, bb_;
        blk_minmax(cmn, cmx, scr, a, bb_);
        if (threadIdx.x == 0) { g_part[4][blockIdx.x] = a; g_part[5][blockIdx.x] = bb_; }
    }
    grid_sync();

    // ---------------- Phase 3: mask + gather + outputs ----------------------
    {
        float cmn, cmx;
        part_minmax(4, 5, scr, cmn, cmx);
        float cinv = 1.0f / (cmx - cmn);

#pragma unroll
        for (int i = 0; i < ITERS; i++) {
            int q = i * QSTRIDE + base;
            int px0 = q * 4;
            int b = px0 / HWSZ;
            int p = px0 - b * HWSZ;

            const int4 w4 = *(const int4*)(g_winner + px0);
            const int wv[4] = {w4.x, w4.y, w4.z, w4.w};

            float4 mask, bx, by, sg;
            float* mv = (float*)&mask;
            float* bxv = (float*)&bx; float* byv = (float*)&by; float* sgv = (float*)&sg;
#pragma unroll
            for (int j = 0; j < 4; j++) {
                mv[j] = ((c_save[i * 4 + j] - cmn) * cinv < THR) ? 1.0f : 0.0f;
                int w = wv[j];
                if (w >= 0) {
                    float4 qd = g_payload[b * HWSZ + w];
                    bxv[j] = qd.x; byv[j] = qd.y; sgv[j] = qd.z;
                } else {
                    bxv[j] = 0.0f; byv[j] = 0.0f; sgv[j] = 0.0f;
                }
            }
            *(float4*)(out + px0)                            = mask;
            *(float4*)(out + NPIX + b * 2 * HWSZ + p)        = bx;
            *(float4*)(out + NPIX + b * 2 * HWSZ + HWSZ + p) = by;
            *(float4*)(out + 3 * NPIX + px0)                 = sg;
        }
    }
}

extern "C" void kernel_launch(void* const* d_in, const int* in_sizes, int n_in,
                              void* d_out, int out_size) {
    const float* flow  = (const float*)d_in[0];
    const float* depth = (const float*)d_in[1];
    const float* Kmat  = (const float*)d_in[2];
    const float* invK  = (const float*)d_in[3];
    const float* pose  = (const float*)d_in[4];
    const int*   seg   = (const int*)d_in[5];
    float* out = (float*)d_out;

    k_fused<<<GRID, TPB>>>(flow, depth, Kmat, invK, pose, seg, out);
}

// round 6
// speedup vs baseline: 1.3360x; 1.3360x over previous
#include <cuda_runtime.h>

// ---------------------------------------------------------------------------
// OpticFlowMask: motion mask + flow inversion (winner election + compact gather)
// B=12, H=192, W=640.
// Output layout (float32): [motion_mask (N)][bwd_flow (2N)][seg_ref (N)]
// Payload: float2 (-fx,-fy) with seg bit packed into LSB of -fx mantissa.
// ---------------------------------------------------------------------------

#define BB    12
#define HH    192
#define WW    640
#define HWSZ  (HH * WW)                 // 122880
#define NPIX  (BB * HWSZ)               // 1474560
#define TPB   256
#define VEC   4
#define PXT   (TPB * VEC)               // 1024 px per block
#define BPB2  (HWSZ / PXT)              // 120 blocks per batch (exact)
#define NBLK2 (BB * BPB2)               // 1440 blocks
#define EPSF  1e-7f
#define THR   0.98f

// reduction slots: 0=fmin 1=fmax 2=smin 3=smax 4=cmin 5=cmax (monotonic-encoded)
__device__ unsigned g_red[6];
__device__ int    g_winner[NPIX];
__device__ float2 g_pay[NPIX];          // (-fx | segbit, -fy)
__device__ float  g_check[NPIX];        // check value per pixel

__device__ __forceinline__ unsigned fenc(float f) {
    unsigned u = __float_as_uint(f);
    return (u & 0x80000000u) ? ~u : (u | 0x80000000u);
}
__device__ __forceinline__ float fdec(unsigned u) {
    unsigned b = (u & 0x80000000u) ? (u & 0x7fffffffu) : ~u;
    return __uint_as_float(b);
}

template <int SMIN, int SMAX>
__device__ __forceinline__ void block_minmax(float vmin, float vmax) {
#pragma unroll
    for (int o = 16; o; o >>= 1) {
        vmin = fminf(vmin, __shfl_xor_sync(0xffffffffu, vmin, o));
        vmax = fmaxf(vmax, __shfl_xor_sync(0xffffffffu, vmax, o));
    }
    __shared__ float sm1[TPB / 32], sm2[TPB / 32];
    int w = threadIdx.x >> 5, l = threadIdx.x & 31;
    if (l == 0) { sm1[w] = vmin; sm2[w] = vmax; }
    __syncthreads();
    if (w == 0) {
        vmin = (l < TPB / 32) ? sm1[l] : __int_as_float(0x7f800000);
        vmax = (l < TPB / 32) ? sm2[l] : __int_as_float(0xff800000);
#pragma unroll
        for (int o = 4; o; o >>= 1) {
            vmin = fminf(vmin, __shfl_xor_sync(0xffffffffu, vmin, o));
            vmax = fmaxf(vmax, __shfl_xor_sync(0xffffffffu, vmax, o));
        }
        if (l == 0) {
            atomicMin(&g_red[SMIN], fenc(vmin));
            atomicMax(&g_red[SMAX], fenc(vmax));
        }
    }
}

// Per-block setup of P = (K @ pose)[:3,:] (12 floats) and invK[:3,:3] (9 floats)
__device__ __forceinline__ void setup_mats(const float* Kmat, const float* invK,
                                           const float* pose, int b,
                                           float* sP, float* siK) {
    int t = threadIdx.x;
    if (t < 12) {
        int i = t >> 2, j = t & 3;
        const float* Kb = Kmat + b * 16;
        const float* Pb = pose + b * 16;
        sP[t] = Kb[i * 4 + 0] * Pb[0 * 4 + j] + Kb[i * 4 + 1] * Pb[1 * 4 + j] +
                Kb[i * 4 + 2] * Pb[2 * 4 + j] + Kb[i * 4 + 3] * Pb[3 * 4 + j];
    } else if (t < 21) {
        int r = (t - 12) / 3, c = (t - 12) % 3;
        siK[t - 12] = invK[b * 16 + r * 4 + c];
    }
    __syncthreads();
}

// static flow for 4 consecutive x positions at fixed y
__device__ __forceinline__ void static_flow4(const float* sP, const float* siK,
                                             float x0, float y, const float4& d4,
                                             float* sx, float* sy) {
    const float dv[4] = {d4.x, d4.y, d4.z, d4.w};
#pragma unroll
    for (int i = 0; i < 4; i++) {
        float x = x0 + (float)i;
        float dx = siK[0] * x + (siK[1] * y + siK[2]);
        float dy = siK[3] * x + (siK[4] * y + siK[5]);
        float dz = siK[6] * x + (siK[7] * y + siK[8]);
        float d = dv[i];
        float cx = d * dx, cy = d * dy, cz = d * dz;
        float c0 = sP[0] * cx + sP[1] * cy + sP[2]  * cz + sP[3];
        float c1 = sP[4] * cx + sP[5] * cy + sP[6]  * cz + sP[7];
        float c2 = sP[8] * cx + sP[9] * cy + sP[10] * cz + sP[11];
        float den = c2 + EPSF;
        sx[i] = c0 / den - x;
        sy[i] = c1 / den - y;
    }
}

__global__ void k_reset() {
    int t = threadIdx.x;
    if (t < 6) g_red[t] = (t & 1) ? 0u : 0xffffffffu;
}

// Pass 1: flow min/max + static min/max; reset winner array.
__global__ void __launch_bounds__(TPB) k_reduce1(
        const float* __restrict__ flow, const float* __restrict__ depth,
        const float* __restrict__ Kmat, const float* __restrict__ invK,
        const float* __restrict__ pose) {
    __shared__ float sP[12], siK[9];
    int b = blockIdx.x / BPB2;
    setup_mats(Kmat, invK, pose, b, sP, siK);

    int p0 = (blockIdx.x - b * BPB2) * PXT + threadIdx.x * VEC;
    int y = p0 / WW, x0 = p0 - y * WW;
    const float4 fx4 = *(const float4*)(flow + b * 2 * HWSZ + p0);
    const float4 fy4 = *(const float4*)(flow + b * 2 * HWSZ + HWSZ + p0);
    const float4 d4  = *(const float4*)(depth + b * HWSZ + p0);
    *(int4*)(g_winner + b * HWSZ + p0) = make_int4(-1, -1, -1, -1);

    float sx[4], sy[4];
    static_flow4(sP, siK, (float)x0, (float)y, d4, sx, sy);

    float fmn = fminf(fminf(fminf(fx4.x, fx4.y), fminf(fx4.z, fx4.w)),
                      fminf(fminf(fy4.x, fy4.y), fminf(fy4.z, fy4.w)));
    float fmx = fmaxf(fmaxf(fmaxf(fx4.x, fx4.y), fmaxf(fx4.z, fx4.w)),
                      fmaxf(fmaxf(fy4.x, fy4.y), fmaxf(fy4.z, fy4.w)));
    float smn = fminf(fminf(fminf(sx[0], sx[1]), fminf(sx[2], sx[3])),
                      fminf(fminf(sy[0], sy[1]), fminf(sy[2], sy[3])));
    float smx = fmaxf(fmaxf(fmaxf(sx[0], sx[1]), fmaxf(sx[2], sx[3])),
                      fmaxf(fmaxf(sy[0], sy[1]), fmaxf(sy[2], sy[3])));

    block_minmax<0, 1>(fmn, fmx);
    block_minmax<2, 3>(smn, smx);
}

// Pass 2: check min/max + winner election + compact payload + check write.
__global__ void __launch_bounds__(TPB) k_reduce2(
        const float* __restrict__ flow, const float* __restrict__ depth,
        const float* __restrict__ Kmat, const float* __restrict__ invK,
        const float* __restrict__ pose, const int* __restrict__ seg) {
    __shared__ float sP[12], siK[9];
    int b = blockIdx.x / BPB2;
    setup_mats(Kmat, invK, pose, b, sP, siK);

    float fmn = fdec(g_red[0]), fmx = fdec(g_red[1]);
    float smn = fdec(g_red[2]), smx = fdec(g_red[3]);
    float finv = 2.0f / (fmx - fmn), sinv = 2.0f / (smx - smn);

    int p0 = (blockIdx.x - b * BPB2) * PXT + threadIdx.x * VEC;
    int idx0 = b * HWSZ + p0;
    int y = p0 / WW, x0 = p0 - y * WW;
    const float4 fx4 = *(const float4*)(flow + b * 2 * HWSZ + p0);
    const float4 fy4 = *(const float4*)(flow + b * 2 * HWSZ + HWSZ + p0);
    const float4 d4  = *(const float4*)(depth + idx0);
    const int4  sg4  = *(const int4*)(seg + idx0);

    float sx[4], sy[4];
    static_flow4(sP, siK, (float)x0, (float)y, d4, sx, sy);

    const float fxv[4] = {fx4.x, fx4.y, fx4.z, fx4.w};
    const float fyv[4] = {fy4.x, fy4.y, fy4.z, fy4.w};
    const int   sgv[4] = {sg4.x, sg4.y, sg4.z, sg4.w};
    float cmn = __int_as_float(0x7f800000), cmx = __int_as_float(0xff800000);
    float4 cv; float* cvv = (float*)&cv;
    float2 pay[4];
#pragma unroll
    for (int i = 0; i < 4; i++) {
        float ddx = (fxv[i] - fmn) * finv - (sx[i] - smn) * sinv;
        float ddy = (fyv[i] - fmn) * finv - (sy[i] - smn) * sinv;
        float c = sqrtf(ddx * ddx + ddy * ddy);
        cvv[i] = c;
        cmn = fminf(cmn, c);
        cmx = fmaxf(cmx, c);
        // pack seg bit into mantissa LSB of -fx (error ~2^-23 relative)
        unsigned ux = (__float_as_uint(-fxv[i]) & ~1u) | (sgv[i] ? 1u : 0u);
        pay[i] = make_float2(__uint_as_float(ux), -fyv[i]);
        // winner election: jnp.round = ties-to-even; clip after int cast
        int cxi = min(max((int)rintf((float)(x0 + i) + fxv[i]), 0), WW - 1);
        int cyi = min(max((int)rintf((float)y + fyv[i]), 0), HH - 1);
        atomicMax(&g_winner[b * HWSZ + cyi * WW + cxi], p0 + i);
    }
    *(float4*)(g_check + idx0) = cv;
    // 4 float2 = 32B contiguous: two float4 stores
    *(float4*)(&g_pay[idx0])     = make_float4(pay[0].x, pay[0].y, pay[1].x, pay[1].y);
    *(float4*)(&g_pay[idx0 + 2]) = make_float4(pay[2].x, pay[2].y, pay[3].x, pay[3].y);

    block_minmax<4, 5>(cmn, cmx);
}

// Pass 3: motion mask from g_check + 8B gather per target.
__global__ void __launch_bounds__(TPB) k_main(float* __restrict__ out) {
    float cmn = fdec(g_red[4]), cmx = fdec(g_red[5]);
    float cinv = 1.0f / (cmx - cmn);

    int b = blockIdx.x / BPB2;
    int p0 = (blockIdx.x - b * BPB2) * PXT + threadIdx.x * VEC;
    int idx0 = b * HWSZ + p0;

    const int4 w4 = *(const int4*)(g_winner + idx0);
    const int wv[4] = {w4.x, w4.y, w4.z, w4.w};
    const float4 c4 = *(const float4*)(g_check + idx0);
    const float cvv[4] = {c4.x, c4.y, c4.z, c4.w};

    float4 mask, bx, by, sg;
    float* mv = (float*)&mask;
    float* bxv = (float*)&bx; float* byv = (float*)&by; float* sgv = (float*)&sg;
#pragma unroll
    for (int i = 0; i < 4; i++) {
        mv[i] = ((cvv[i] - cmn) * cinv < THR) ? 1.0f : 0.0f;
        int w = wv[i];
        if (w >= 0) {
            float2 q = g_pay[b * HWSZ + w];
            bxv[i] = q.x;
            byv[i] = q.y;
            sgv[i] = (__float_as_uint(q.x) & 1u) ? 1.0f : 0.0f;
        } else {
            bxv[i] = 0.0f; byv[i] = 0.0f; sgv[i] = 0.0f;
        }
    }
    *(float4*)(out + idx0)                            = mask;
    *(float4*)(out + NPIX + b * 2 * HWSZ + p0)        = bx;
    *(float4*)(out + NPIX + b * 2 * HWSZ + HWSZ + p0) = by;
    *(float4*)(out + 3 * NPIX + idx0)                 = sg;
}

extern "C" void kernel_launch(void* const* d_in, const int* in_sizes, int n_in,
                              void* d_out, int out_size) {
    const float* flow  = (const float*)d_in[0];
    const float* depth = (const float*)d_in[1];
    const float* Kmat  = (const float*)d_in[2];
    const float* invK  = (const float*)d_in[3];
    const float* pose  = (const float*)d_in[4];
    const int*   seg   = (const int*)d_in[5];
    float* out = (float*)d_out;

    k_reset<<<1, 32>>>();
    k_reduce1<<<NBLK2, TPB>>>(flow, depth, Kmat, invK, pose);
    k_reduce2<<<NBLK2, TPB>>>(flow, depth, Kmat, invK, pose, seg);
    k_main<<<NBLK2, TPB>>>(out);
}

// round 7
// speedup vs baseline: 1.4326x; 1.0723x over previous
#include <cuda_runtime.h>

// ---------------------------------------------------------------------------
// OpticFlowMask: motion mask + flow inversion (winner election + compact gather)
// B=12, H=192, W=640. 2 VEC4 chunks per thread for MLP.
// Output layout (float32): [motion_mask (N)][bwd_flow (2N)][seg_ref (N)]
// Payload: float2 (-fx,-fy) with seg bit packed into LSB of -fx mantissa.
// ---------------------------------------------------------------------------

#define BB    12
#define HH    192
#define WW    640
#define HWSZ  (HH * WW)                 // 122880
#define NPIX  (BB * HWSZ)               // 1474560
#define TPB   256
#define VEC   4
#define NCH   2                         // chunks per thread
#define CHOFF (TPB * VEC)               // 1024 px between chunks
#define PXT   (TPB * VEC * NCH)         // 2048 px per block
#define BPB2  (HWSZ / PXT)              // 60 blocks per batch (exact)
#define NBLK2 (BB * BPB2)               // 720 blocks
#define EPSF  1e-7f
#define THR   0.98f

// reduction slots: 0=fmin 1=fmax 2=smin 3=smax 4=cmin 5=cmax (monotonic-encoded)
__device__ unsigned g_red[6];
__device__ int    g_winner[NPIX];
__device__ float2 g_pay[NPIX];          // (-fx | segbit, -fy)
__device__ float  g_check[NPIX];        // check value per pixel

__device__ __forceinline__ unsigned fenc(float f) {
    unsigned u = __float_as_uint(f);
    return (u & 0x80000000u) ? ~u : (u | 0x80000000u);
}
__device__ __forceinline__ float fdec(unsigned u) {
    unsigned b = (u & 0x80000000u) ? (u & 0x7fffffffu) : ~u;
    return __uint_as_float(b);
}

template <int SMIN, int SMAX>
__device__ __forceinline__ void block_minmax(float vmin, float vmax) {
#pragma unroll
    for (int o = 16; o; o >>= 1) {
        vmin = fminf(vmin, __shfl_xor_sync(0xffffffffu, vmin, o));
        vmax = fmaxf(vmax, __shfl_xor_sync(0xffffffffu, vmax, o));
    }
    __shared__ float sm1[TPB / 32], sm2[TPB / 32];
    int w = threadIdx.x >> 5, l = threadIdx.x & 31;
    if (l == 0) { sm1[w] = vmin; sm2[w] = vmax; }
    __syncthreads();
    if (w == 0) {
        vmin = (l < TPB / 32) ? sm1[l] : __int_as_float(0x7f800000);
        vmax = (l < TPB / 32) ? sm2[l] : __int_as_float(0xff800000);
#pragma unroll
        for (int o = 4; o; o >>= 1) {
            vmin = fminf(vmin, __shfl_xor_sync(0xffffffffu, vmin, o));
            vmax = fmaxf(vmax, __shfl_xor_sync(0xffffffffu, vmax, o));
        }
        if (l == 0) {
            atomicMin(&g_red[SMIN], fenc(vmin));
            atomicMax(&g_red[SMAX], fenc(vmax));
        }
    }
}

// Per-block setup of P = (K @ pose)[:3,:] (12 floats) and invK[:3,:3] (9 floats)
__device__ __forceinline__ void setup_mats(const float* Kmat, const float* invK,
                                           const float* pose, int b,
                                           float* sP, float* siK) {
    int t = threadIdx.x;
    if (t < 12) {
        int i = t >> 2, j = t & 3;
        const float* Kb = Kmat + b * 16;
        const float* Pb = pose + b * 16;
        sP[t] = Kb[i * 4 + 0] * Pb[0 * 4 + j] + Kb[i * 4 + 1] * Pb[1 * 4 + j] +
                Kb[i * 4 + 2] * Pb[2 * 4 + j] + Kb[i * 4 + 3] * Pb[3 * 4 + j];
    } else if (t < 21) {
        int r = (t - 12) / 3, c = (t - 12) % 3;
        siK[t - 12] = invK[b * 16 + r * 4 + c];
    }
    __syncthreads();
}

// static flow for 4 consecutive x positions at fixed y
__device__ __forceinline__ void static_flow4(const float* sP, const float* siK,
                                             float x0, float y, const float4& d4,
                                             float* sx, float* sy) {
    const float dv[4] = {d4.x, d4.y, d4.z, d4.w};
#pragma unroll
    for (int i = 0; i < 4; i++) {
        float x = x0 + (float)i;
        float dx = siK[0] * x + (siK[1] * y + siK[2]);
        float dy = siK[3] * x + (siK[4] * y + siK[5]);
        float dz = siK[6] * x + (siK[7] * y + siK[8]);
        float d = dv[i];
        float cx = d * dx, cy = d * dy, cz = d * dz;
        float c0 = sP[0] * cx + sP[1] * cy + sP[2]  * cz + sP[3];
        float c1 = sP[4] * cx + sP[5] * cy + sP[6]  * cz + sP[7];
        float c2 = sP[8] * cx + sP[9] * cy + sP[10] * cz + sP[11];
        float den = c2 + EPSF;
        sx[i] = c0 / den - x;
        sy[i] = c1 / den - y;
    }
}

__global__ void k_reset() {
    int t = threadIdx.x;
    if (t < 6) g_red[t] = (t & 1) ? 0u : 0xffffffffu;
}

// Pass 1: flow min/max + static min/max; reset winner array.
__global__ void __launch_bounds__(TPB) k_reduce1(
        const float* __restrict__ flow, const float* __restrict__ depth,
        const float* __restrict__ Kmat, const float* __restrict__ invK,
        const float* __restrict__ pose) {
    __shared__ float sP[12], siK[9];
    int b = blockIdx.x / BPB2;
    setup_mats(Kmat, invK, pose, b, sP, siK);

    int pb = (blockIdx.x - b * BPB2) * PXT + threadIdx.x * VEC;
    const float* fb = flow + b * 2 * HWSZ;

    // front-batch all loads (2 independent chunks)
    float4 fx4[NCH], fy4[NCH], d4[NCH];
#pragma unroll
    for (int h = 0; h < NCH; h++) {
        int p = pb + h * CHOFF;
        fx4[h] = *(const float4*)(fb + p);
        fy4[h] = *(const float4*)(fb + HWSZ + p);
        d4[h]  = *(const float4*)(depth + b * HWSZ + p);
        *(int4*)(g_winner + b * HWSZ + p) = make_int4(-1, -1, -1, -1);
    }

    float fmn = __int_as_float(0x7f800000), fmx = __int_as_float(0xff800000);
    float smn = fmn, smx = fmx;
#pragma unroll
    for (int h = 0; h < NCH; h++) {
        int p = pb + h * CHOFF;
        int y = p / WW, x0 = p - y * WW;
        float sx[4], sy[4];
        static_flow4(sP, siK, (float)x0, (float)y, d4[h], sx, sy);
        fmn = fminf(fmn, fminf(fminf(fx4[h].x, fx4[h].y), fminf(fx4[h].z, fx4[h].w)));
        fmn = fminf(fmn, fminf(fminf(fy4[h].x, fy4[h].y), fminf(fy4[h].z, fy4[h].w)));
        fmx = fmaxf(fmx, fmaxf(fmaxf(fx4[h].x, fx4[h].y), fmaxf(fx4[h].z, fx4[h].w)));
        fmx = fmaxf(fmx, fmaxf(fmaxf(fy4[h].x, fy4[h].y), fmaxf(fy4[h].z, fy4[h].w)));
        smn = fminf(smn, fminf(fminf(fminf(sx[0], sx[1]), fminf(sx[2], sx[3])),
                               fminf(fminf(sy[0], sy[1]), fminf(sy[2], sy[3]))));
        smx = fmaxf(smx, fmaxf(fmaxf(fmaxf(sx[0], sx[1]), fmaxf(sx[2], sx[3])),
                               fmaxf(fmaxf(sy[0], sy[1]), fmaxf(sy[2], sy[3]))));
    }

    block_minmax<0, 1>(fmn, fmx);
    block_minmax<2, 3>(smn, smx);
}

// Pass 2: check min/max + winner election + compact payload + check write.
__global__ void __launch_bounds__(TPB) k_reduce2(
        const float* __restrict__ flow, const float* __restrict__ depth,
        const float* __restrict__ Kmat, const float* __restrict__ invK,
        const float* __restrict__ pose, const int* __restrict__ seg) {
    __shared__ float sP[12], siK[9];
    int b = blockIdx.x / BPB2;
    setup_mats(Kmat, invK, pose, b, sP, siK);

    float fmn = fdec(g_red[0]), fmx = fdec(g_red[1]);
    float smn = fdec(g_red[2]), smx = fdec(g_red[3]);
    float finv = 2.0f / (fmx - fmn), sinv = 2.0f / (smx - smn);

    int pb = (blockIdx.x - b * BPB2) * PXT + threadIdx.x * VEC;
    const float* fb = flow + b * 2 * HWSZ;

    float4 fx4[NCH], fy4[NCH], d4[NCH];
    int4 sg4[NCH];
#pragma unroll
    for (int h = 0; h < NCH; h++) {
        int p = pb + h * CHOFF;
        fx4[h] = *(const float4*)(fb + p);
        fy4[h] = *(const float4*)(fb + HWSZ + p);
        d4[h]  = *(const float4*)(depth + b * HWSZ + p);
        sg4[h] = *(const int4*)(seg + b * HWSZ + p);
    }

    float cmn = __int_as_float(0x7f800000), cmx = __int_as_float(0xff800000);
#pragma unroll
    for (int h = 0; h < NCH; h++) {
        int p = pb + h * CHOFF;
        int idx = b * HWSZ + p;
        int y = p / WW, x0 = p - y * WW;
        float sx[4], sy[4];
        static_flow4(sP, siK, (float)x0, (float)y, d4[h], sx, sy);

        const float fxv[4] = {fx4[h].x, fx4[h].y, fx4[h].z, fx4[h].w};
        const float fyv[4] = {fy4[h].x, fy4[h].y, fy4[h].z, fy4[h].w};
        const int   sgv[4] = {sg4[h].x, sg4[h].y, sg4[h].z, sg4[h].w};
        float4 cv; float* cvv = (float*)&cv;
        float2 pay[4];
#pragma unroll
        for (int i = 0; i < 4; i++) {
            float ddx = (fxv[i] - fmn) * finv - (sx[i] - smn) * sinv;
            float ddy = (fyv[i] - fmn) * finv - (sy[i] - smn) * sinv;
            float c = sqrtf(ddx * ddx + ddy * ddy);
            cvv[i] = c;
            cmn = fminf(cmn, c);
            cmx = fmaxf(cmx, c);
            // pack seg bit into mantissa LSB of -fx (error ~2^-23 relative)
            unsigned ux = (__float_as_uint(-fxv[i]) & ~1u) | (sgv[i] ? 1u : 0u);
            pay[i] = make_float2(__uint_as_float(ux), -fyv[i]);
            // winner election: jnp.round = ties-to-even; clip after int cast
            int cxi = min(max((int)rintf((float)(x0 + i) + fxv[i]), 0), WW - 1);
            int cyi = min(max((int)rintf((float)y + fyv[i]), 0), HH - 1);
            atomicMax(&g_winner[b * HWSZ + cyi * WW + cxi], p + i);
        }
        *(float4*)(g_check + idx) = cv;
        *(float4*)(&g_pay[idx])     = make_float4(pay[0].x, pay[0].y, pay[1].x, pay[1].y);
        *(float4*)(&g_pay[idx + 2]) = make_float4(pay[2].x, pay[2].y, pay[3].x, pay[3].y);
    }

    block_minmax<4, 5>(cmn, cmx);
}

// Pass 3: motion mask from g_check + 8B gather per target (2 chunks, MLP=8+).
__global__ void __launch_bounds__(TPB) k_main(float* __restrict__ out) {
    float cmn = fdec(g_red[4]), cmx = fdec(g_red[5]);
    float cinv = 1.0f / (cmx - cmn);

    int b = blockIdx.x / BPB2;
    int pb = (blockIdx.x - b * BPB2) * PXT + threadIdx.x * VEC;

    // front-batch winner + check loads for both chunks (streaming: no reuse)
    int4 w4[NCH]; float4 c4[NCH];
#pragma unroll
    for (int h = 0; h < NCH; h++) {
        int idx = b * HWSZ + pb + h * CHOFF;
        w4[h] = __ldcs((const int4*)(g_winner + idx));
        c4[h] = __ldcs((const float4*)(g_check + idx));
    }

#pragma unroll
    for (int h = 0; h < NCH; h++) {
        int p = pb + h * CHOFF;
        int idx = b * HWSZ + p;
        const int wv[4] = {w4[h].x, w4[h].y, w4[h].z, w4[h].w};
        const float cvv[4] = {c4[h].x, c4[h].y, c4[h].z, c4[h].w};

        // issue all 4 gathers before consuming
        float2 q[4];
#pragma unroll
        for (int i = 0; i < 4; i++)
            q[i] = (wv[i] >= 0) ? g_pay[b * HWSZ + wv[i]] : make_float2(0.f, 0.f);

        float4 mask, bx, by, sg;
        float* mv = (float*)&mask;
        float* bxv = (float*)&bx; float* byv = (float*)&by; float* sgv = (float*)&sg;
#pragma unroll
        for (int i = 0; i < 4; i++) {
            mv[i] = ((cvv[i] - cmn) * cinv < THR) ? 1.0f : 0.0f;
            if (wv[i] >= 0) {
                bxv[i] = q[i].x;
                byv[i] = q[i].y;
                sgv[i] = (__float_as_uint(q[i].x) & 1u) ? 1.0f : 0.0f;
            } else {
                bxv[i] = 0.0f; byv[i] = 0.0f; sgv[i] = 0.0f;
            }
        }
        __stcs((float4*)(out + idx),                           mask);
        __stcs((float4*)(out + NPIX + b * 2 * HWSZ + p),        bx);
        __stcs((float4*)(out + NPIX + b * 2 * HWSZ + HWSZ + p), by);
        __stcs((float4*)(out + 3 * NPIX + idx),                 sg);
    }
}

extern "C" void kernel_launch(void* const* d_in, const int* in_sizes, int n_in,
                              void* d_out, int out_size) {
    const float* flow  = (const float*)d_in[0];
    const float* depth = (const float*)d_in[1];
    const float* Kmat  = (const float*)d_in[2];
    const float* invK  = (const float*)d_in[3];
    const float* pose  = (const float*)d_in[4];
    const int*   seg   = (const int*)d_in[5];
    float* out = (float*)d_out;

    k_reset<<<1, 32>>>();
    k_reduce1<<<NBLK2, TPB>>>(flow, depth, Kmat, invK, pose);
    k_reduce2<<<NBLK2, TPB>>>(flow, depth, Kmat, invK, pose, seg);
    k_main<<<NBLK2, TPB>>>(out);
}